// round 15
// baseline (speedup 1.0000x reference)
#include <cuda_runtime.h>
#include <cuda_fp16.h>
#include <math.h>
#include <string.h>

#define TWO_PI_F 6.283185307179586f

#define OUT1_ELEMS 67108864
#define O_DIM   512
#define CIN_DIM 512
#define K_DIM   16
#define NI_DIM  16
#define NO_DIM  16
#define KS_DIM  7

#define ROT_TOTAL   (O_DIM * NO_DIM * KS_DIM * KS_DIM) // 401408
#define ROT_BLOCKS  (ROT_TOTAL / 128)                  // 3136 (exact)
#define LERP_BLOCKS (O_DIM * (CIN_DIM / 32))           // 8192: (o, c_block of 32)

// bit-cast helpers
__device__ __forceinline__ unsigned int h2_as_u32(__half2 h) {
    unsigned int u; memcpy(&u, &h, 4); return u;
}
__device__ __forceinline__ __half2 u32_as_h2(unsigned int u) {
    __half2 h; memcpy(&h, &u, 4); return h;
}

// ---------------------------------------------------------------------------
// Fused kernel, 128-thread blocks (11 CTAs/SM at ~44 regs -> 44 warps/SM).
//  Blocks [0, ROT_BLOCKS): rotated bilinear resample (tiny; runs first so the
//   grid tail is uniform lerp blocks).
//  Blocks [ROT_BLOCKS, +LERP_BLOCKS): weight_H_out [o, ni, c, no], 32 c/block.
//   fp16 pair table: tab[i0*32 + g*4 + noq] (uint4) = 4x half2 =
//   (W[row][i0],W[row][i0+1]) for rows {g, g+8, g+16, g+24}. One LDS.128
//   feeds FOUR outputs; octet bank-quads (4*c_idx+noq) mod 8 all distinct ->
//   conflict-free for any runtime i0. d = in_H - out_H in (-2pi,2pi) =>
//   python-mod == (d<0 ? d+2pi : d); no fmodf. Warp covers 4 ni (full
//   unroll, per-n2 recompute keeps all reg-array indexing static).
//   Stores: octet writes noq*4 + c_idx*16 floats = dense 128B line.
// ---------------------------------------------------------------------------
__global__ __launch_bounds__(128) void gsep_fused_kernel(
    const float* __restrict__ in_H,
    const float* __restrict__ out_H,
    const float* __restrict__ weight_H,   // [512, 512, 16]
    const float* __restrict__ weight,     // [512, 1, 7, 7]
    const float* __restrict__ grid_Rn,    // [7, 7, 2]
    const float* __restrict__ mask,       // [7, 7]
    float* __restrict__ out)              // out1 | out2
{
    const int b = blockIdx.x;
    const int t = threadIdx.x;

    if (b >= ROT_BLOCKS) {
        __shared__ unsigned int praw[32 * 17];   // half2 pairs, [row][k]
        __shared__ uint4        tab [512];       // [i0(16)][g(8)][noq(4)] = 8KB

        const int bl     = b - ROT_BLOCKS;
        const int o      = bl >> 4;
        const int c_base = (bl & 15) * 32;
        const int lane   = t & 31;
        const int warp   = t >> 5;        // 0..3
        const int noq    = lane & 3;      // no quad (dense stores)
        const int c_idx  = lane >> 2;     // 0..7

        // --- stage: global float4 -> fp16 (k,k+1) pairs in praw ---
        {
            const float4 v = ((const float4*)(weight_H
                              + ((size_t)o * 512 + c_base) * 16))[t];
            const int r = t >> 2, q = t & 3;
            float down_x = __shfl_down_sync(0xffffffffu, v.x, 1);
            float base_x = __shfl_sync(0xffffffffu, v.x, lane & ~3);
            float nxt = (q == 3) ? base_x : down_x;
            unsigned int* d = praw + r * 17 + q * 4;
            d[0] = h2_as_u32(__floats2half2_rn(v.x, v.y));
            d[1] = h2_as_u32(__floats2half2_rn(v.y, v.z));
            d[2] = h2_as_u32(__floats2half2_rn(v.z, v.w));
            d[3] = h2_as_u32(__floats2half2_rn(v.w, nxt));
        }

        // preload the 4 out_H values this thread uses
        float oh[4];
        #pragma unroll
        for (int j = 0; j < 4; j++) oh[j] = __ldg(out_H + noq * 4 + j);

        __syncthreads();

        // --- build tab: 512 entries, 4 per thread ---
        #pragma unroll
        for (int e = t; e < 512; e += 128) {
            const int k = e >> 5;            // 0..15
            const int g = (e >> 2) & 7;      // 0..7
            tab[e] = make_uint4(praw[(g     ) * 17 + k],
                                praw[(g +  8) * 17 + k],
                                praw[(g + 16) * 17 + k],
                                praw[(g + 24) * 17 + k]);
        }
        __syncthreads();

        // --- hot loop: warp covers 4 ni, full unroll (static indexing) ---
        #pragma unroll
        for (int n2 = 0; n2 < 4; n2++) {
            const int ni = warp * 4 + n2;
            int i0[4]; float fr[4];
            const float ih = __ldg(in_H + ni);
            #pragma unroll
            for (int j = 0; j < 4; j++) {
                float d = ih - oh[j];            // in (-2pi, 2pi)
                if (d < 0.0f) d += TWO_PI_F;     // == python mod here
                float tt = d * (16.0f / TWO_PI_F);
                float fl = floorf(tt);
                i0[j] = (((int)fl) & 15) << 5;   // pre-shifted table offset
                fr[j] = tt - fl;
            }
            float* obase = out + ((((size_t)o * 16 + ni) * 512 + c_base) << 4)
                               + noq * 4;
            float res[4][4];
            #pragma unroll
            for (int j = 0; j < 4; j++) {
                const uint4 E = tab[i0[j] + (c_idx << 2) + noq];
                const float f = fr[j];
                float2 a;
                a = __half22float2(u32_as_h2(E.x));
                res[0][j] = fmaf(f, a.y - a.x, a.x);
                a = __half22float2(u32_as_h2(E.y));
                res[1][j] = fmaf(f, a.y - a.x, a.x);
                a = __half22float2(u32_as_h2(E.z));
                res[2][j] = fmaf(f, a.y - a.x, a.x);
                a = __half22float2(u32_as_h2(E.w));
                res[3][j] = fmaf(f, a.y - a.x, a.x);
            }
            #pragma unroll
            for (int m = 0; m < 4; m++) {
                const int c_local = 8 * m + c_idx;
                __stcs((float4*)(obase + ((size_t)c_local << 4)),
                       make_float4(res[m][0], res[m][1],
                                   res[m][2], res[m][3]));
            }
        }
        return;
    }

    // -------------------- rotated bilinear resample part --------------------
    const int idx = b * 128 + t;     // ROT_TOTAL = ROT_BLOCKS*128 exactly

    const int pix = idx % (KS_DIM * KS_DIM);
    const int on  = idx / (KS_DIM * KS_DIM);
    const int no  = on & 15;
    const int o   = on >> 4;

    const float gx = grid_Rn[pix * 2 + 0];
    const float gy = grid_Rn[pix * 2 + 1];

    const float ang = -out_H[no];
    float sn, cs;
    sincosf(ang, &sn, &cs);
    const float xr = cs * gx - sn * gy;
    const float yr = sn * gx + cs * gy;

    const float x = (xr + 1.0f) * 0.5f * (float)(KS_DIM - 1);
    const float y = (yr + 1.0f) * 0.5f * (float)(KS_DIM - 1);
    const float x0f = floorf(x), y0f = floorf(y);
    const float wx = x - x0f,    wy = y - y0f;
    const int x0 = (int)x0f,     y0 = (int)y0f;

    const float* img = weight + o * (KS_DIM * KS_DIM);

    auto g = [&](int yy, int xx) -> float {
        if (yy < 0 || yy >= KS_DIM || xx < 0 || xx >= KS_DIM) return 0.0f;
        return img[yy * KS_DIM + xx];
    };

    const float v = (1.0f - wy) * (1.0f - wx) * g(y0,     x0)
                  + (1.0f - wy) * wx          * g(y0,     x0 + 1)
                  + wy          * (1.0f - wx) * g(y0 + 1, x0)
                  + wy          * wx          * g(y0 + 1, x0 + 1);

    out[OUT1_ELEMS + idx] = mask[pix] * v;
}

// ---------------------------------------------------------------------------
extern "C" void kernel_launch(void* const* d_in, const int* in_sizes, int n_in,
                              void* d_out, int out_size)
{
    const float* in_H     = (const float*)d_in[0];  // [16, 1]
    const float* out_H    = (const float*)d_in[1];  // [16, 1]
    const float* weight_H = (const float*)d_in[2];  // [512, 512, 16]
    const float* weight   = (const float*)d_in[3];  // [512, 1, 7, 7]
    // d_in[4] = grid_H (uniform grid, implicit; unused)
    const float* grid_Rn  = (const float*)d_in[5];  // [7, 7, 2]
    const float* mask     = (const float*)d_in[6];  // [7, 7]

    gsep_fused_kernel<<<ROT_BLOCKS + LERP_BLOCKS, 128>>>(
        in_H, out_H, weight_H, weight, grid_Rn, mask, (float*)d_out);
}

// round 17
// speedup vs baseline: 1.0028x; 1.0028x over previous
#include <cuda_runtime.h>
#include <cuda_fp16.h>
#include <math.h>
#include <string.h>

#define TWO_PI_F 6.283185307179586f

#define OUT1_ELEMS 67108864
#define O_DIM   512
#define CIN_DIM 512
#define K_DIM   16
#define NI_DIM  16
#define NO_DIM  16
#define KS_DIM  7

#define LERP_BLOCKS (O_DIM * (CIN_DIM / 128))          // 2048: (o, c_block of 128)
#define ROT_TOTAL   (O_DIM * NO_DIM * KS_DIM * KS_DIM) // 401408
#define ROT_BLOCKS  ((ROT_TOTAL + 255) / 256)          // 1568

// bit-cast helpers
__device__ __forceinline__ unsigned int h2_as_u32(__half2 h) {
    unsigned int u; memcpy(&u, &h, 4); return u;
}
__device__ __forceinline__ __half2 u32_as_h2(unsigned int u) {
    __half2 h; memcpy(&h, &u, 4); return h;
}

// ---------------------------------------------------------------------------
// Fused kernel (R14 structure, 128 c-rows/block: per-block overhead halved).
//  Blocks [0, LERP_BLOCKS): weight_H_out [o, ni, c, no].
//   fp16 pair table: tab[i0*128 + g*4 + noq] (uint4) = 4x half2 =
//   (W[row][i0],W[row][i0+1]) for rows {g, g+32, g+64, g+96}, g in 0..31.
//   One LDS.128 feeds FOUR outputs; octet bank-quads (4g+noq) mod 8 all
//   distinct (i0*128 == 0 mod 8) -> conflict-free for any runtime i0.
//   d = in_H - out_H in (-2pi,2pi) => python-mod == (d<0 ? d+2pi : d).
//   Full n2 unroll + per-n2 recompute keeps all reg-array indexing static.
//   Stores: warp STG.128 set = dense 512B run.
//  Blocks [LERP_BLOCKS, ...): rotated bilinear resample (tiny).
// ---------------------------------------------------------------------------
__global__ __launch_bounds__(256) void gsep_fused_kernel(
    const float* __restrict__ in_H,
    const float* __restrict__ out_H,
    const float* __restrict__ weight_H,   // [512, 512, 16]
    const float* __restrict__ weight,     // [512, 1, 7, 7]
    const float* __restrict__ grid_Rn,    // [7, 7, 2]
    const float* __restrict__ mask,       // [7, 7]
    float* __restrict__ out)              // out1 | out2
{
    const int b = blockIdx.x;
    const int t = threadIdx.x;

    if (b < LERP_BLOCKS) {
        __shared__ unsigned int praw[128 * 17];  // half2 pairs, [row][k], 8.7KB
        __shared__ uint4        tab [2048];      // [i0(16)][g(32)][noq(4)] = 32KB

        const int o      = b >> 2;
        const int c_base = (b & 3) * 128;
        const int lane   = t & 31;
        const int warp   = t >> 5;        // 0..7
        const int noq    = lane & 3;      // no quad (dense stores)
        const int c_idx  = lane >> 2;     // 0..7

        // --- stage: 128 rows x 16 floats -> fp16 (k,k+1) pairs (2 iters) ---
        #pragma unroll
        for (int i = t; i < 512; i += 256) {
            const float4 v = ((const float4*)(weight_H
                              + ((size_t)o * 512 + c_base) * 16))[i];
            const int r = i >> 2, q = i & 3;   // q == t&3 (256 % 4 == 0)
            float down_x = __shfl_down_sync(0xffffffffu, v.x, 1);
            float base_x = __shfl_sync(0xffffffffu, v.x, lane & ~3);
            float nxt = (q == 3) ? base_x : down_x;
            unsigned int* d = praw + r * 17 + q * 4;
            d[0] = h2_as_u32(__floats2half2_rn(v.x, v.y));
            d[1] = h2_as_u32(__floats2half2_rn(v.y, v.z));
            d[2] = h2_as_u32(__floats2half2_rn(v.z, v.w));
            d[3] = h2_as_u32(__floats2half2_rn(v.w, nxt));
        }

        // preload the 4 out_H values this thread uses
        float oh[4];
        #pragma unroll
        for (int j = 0; j < 4; j++) oh[j] = __ldg(out_H + noq * 4 + j);

        __syncthreads();

        // --- build tab: 2048 entries, 8 per thread ---
        #pragma unroll
        for (int e = t; e < 2048; e += 256) {
            const int k = e >> 7;            // 0..15
            const int g = (e >> 2) & 31;     // 0..31
            tab[e] = make_uint4(praw[(g     ) * 17 + k],
                                praw[(g + 32) * 17 + k],
                                praw[(g + 64) * 17 + k],
                                praw[(g + 96) * 17 + k]);
        }
        __syncthreads();

        // --- hot loop: full n2 unroll (static indexing) ---
        #pragma unroll
        for (int n2 = 0; n2 < 2; n2++) {
            const int ni = warp * 2 + n2;
            int i0[4]; float fr[4];
            const float ih = __ldg(in_H + ni);
            #pragma unroll
            for (int j = 0; j < 4; j++) {
                float d = ih - oh[j];            // in (-2pi, 2pi)
                if (d < 0.0f) d += TWO_PI_F;     // == python mod here
                float tt = d * (16.0f / TWO_PI_F);
                float fl = floorf(tt);
                i0[j] = (((int)fl) & 15) << 7;   // pre-shifted table offset
                fr[j] = tt - fl;
            }
            float* obase = out + ((((size_t)o * 16 + ni) * 512 + c_base) << 4)
                               + noq * 4;
            #pragma unroll
            for (int chunk = 0; chunk < 4; chunk++) {
                const int g = chunk * 8 + c_idx;
                float res[4][4];
                #pragma unroll
                for (int j = 0; j < 4; j++) {
                    const uint4 E = tab[i0[j] + (g << 2) + noq];
                    const float f = fr[j];
                    float2 a;
                    a = __half22float2(u32_as_h2(E.x));
                    res[0][j] = fmaf(f, a.y - a.x, a.x);
                    a = __half22float2(u32_as_h2(E.y));
                    res[1][j] = fmaf(f, a.y - a.x, a.x);
                    a = __half22float2(u32_as_h2(E.z));
                    res[2][j] = fmaf(f, a.y - a.x, a.x);
                    a = __half22float2(u32_as_h2(E.w));
                    res[3][j] = fmaf(f, a.y - a.x, a.x);
                }
                #pragma unroll
                for (int m = 0; m < 4; m++) {
                    const int c_local = 32 * m + g;
                    __stcs((float4*)(obase + ((size_t)c_local << 4)),
                           make_float4(res[m][0], res[m][1],
                                       res[m][2], res[m][3]));
                }
            }
        }
        return;
    }

    // -------------------- rotated bilinear resample part --------------------
    const int idx = (b - LERP_BLOCKS) * 256 + t;
    if (idx >= ROT_TOTAL) return;

    const int pix = idx % (KS_DIM * KS_DIM);
    const int on  = idx / (KS_DIM * KS_DIM);
    const int no  = on & 15;
    const int o   = on >> 4;

    const float gx = grid_Rn[pix * 2 + 0];
    const float gy = grid_Rn[pix * 2 + 1];

    const float ang = -out_H[no];
    float sn, cs;
    sincosf(ang, &sn, &cs);
    const float xr = cs * gx - sn * gy;
    const float yr = sn * gx + cs * gy;

    const float x = (xr + 1.0f) * 0.5f * (float)(KS_DIM - 1);
    const float y = (yr + 1.0f) * 0.5f * (float)(KS_DIM - 1);
    const float x0f = floorf(x), y0f = floorf(y);
    const float wx = x - x0f,    wy = y - y0f;
    const int x0 = (int)x0f,     y0 = (int)y0f;

    const float* img = weight + o * (KS_DIM * KS_DIM);

    auto g = [&](int yy, int xx) -> float {
        if (yy < 0 || yy >= KS_DIM || xx < 0 || xx >= KS_DIM) return 0.0f;
        return img[yy * KS_DIM + xx];
    };

    const float v = (1.0f - wy) * (1.0f - wx) * g(y0,     x0)
                  + (1.0f - wy) * wx          * g(y0,     x0 + 1)
                  + wy          * (1.0f - wx) * g(y0 + 1, x0)
                  + wy          * wx          * g(y0 + 1, x0 + 1);

    out[OUT1_ELEMS + idx] = mask[pix] * v;
}

// ---------------------------------------------------------------------------
extern "C" void kernel_launch(void* const* d_in, const int* in_sizes, int n_in,
                              void* d_out, int out_size)
{
    const float* in_H     = (const float*)d_in[0];  // [16, 1]
    const float* out_H    = (const float*)d_in[1];  // [16, 1]
    const float* weight_H = (const float*)d_in[2];  // [512, 512, 16]
    const float* weight   = (const float*)d_in[3];  // [512, 1, 7, 7]
    // d_in[4] = grid_H (uniform grid, implicit; unused)
    const float* grid_Rn  = (const float*)d_in[5];  // [7, 7, 2]
    const float* mask     = (const float*)d_in[6];  // [7, 7]

    gsep_fused_kernel<<<LERP_BLOCKS + ROT_BLOCKS, 256>>>(
        in_H, out_H, weight_H, weight, grid_Rn, mask, (float*)d_out);
}